// round 1
// baseline (speedup 1.0000x reference)
#include <cuda_runtime.h>
#include <math.h>

#define N_TOK 4096
#define D_DIM 1024
#define H_DIM 2048
#define E_NUM 8

#define BM 128
#define BN 128
#define BK 8
#define TM 8
#define TN 8
#define NTHREADS 256

// ---------------- device scratch (no allocations allowed) ----------------
__device__ int   g_cnt[E_NUM];                       // tokens per expert
__device__ int   g_asg[E_NUM][N_TOK];                // (token<<1)|slot per assignment
__device__ float g_gate[E_NUM][N_TOK];               // gate weight per assignment
__device__ float g_h[(size_t)N_TOK * 2 * H_DIM];     // 64MB: silu(x@w1^T+b1), indexed by (token*2+slot)

// ---------------- init ----------------
__global__ void init_kernel() {
    if (threadIdx.x < E_NUM) g_cnt[threadIdx.x] = 0;
}

// ---------------- gating: one warp per token ----------------
__global__ void gating_kernel(const float* __restrict__ x,
                              const float* __restrict__ gw) {
    int tok  = (blockIdx.x * blockDim.x + threadIdx.x) >> 5;
    int lane = threadIdx.x & 31;
    if (tok >= N_TOK) return;
    const float* xr = x + (size_t)tok * D_DIM;

    float acc[E_NUM];
#pragma unroll
    for (int e = 0; e < E_NUM; e++) acc[e] = 0.f;

    for (int d = lane; d < D_DIM; d += 32) {
        float xv = xr[d];
#pragma unroll
        for (int e = 0; e < E_NUM; e++)
            acc[e] = fmaf(xv, __ldg(gw + (size_t)e * D_DIM + d), acc[e]);
    }
#pragma unroll
    for (int e = 0; e < E_NUM; e++) {
#pragma unroll
        for (int off = 16; off > 0; off >>= 1)
            acc[e] += __shfl_xor_sync(0xffffffffu, acc[e], off);
    }
    if (lane == 0) {
        // top-2, ties -> lower index (matches jax.lax.top_k)
        int i0 = 0; float v0 = acc[0];
#pragma unroll
        for (int e = 1; e < E_NUM; e++)
            if (acc[e] > v0) { v0 = acc[e]; i0 = e; }
        int i1 = -1; float v1 = -3.4e38f;
#pragma unroll
        for (int e = 0; e < E_NUM; e++)
            if (e != i0 && acc[e] > v1) { v1 = acc[e]; i1 = e; }

        // softmax over [v0, v1] (v0 is the max)
        float ex = expf(v1 - v0);
        float s  = 1.f + ex;
        float g0 = 1.f / s;
        float g1 = ex / s;

        int p0 = atomicAdd(&g_cnt[i0], 1);
        g_asg[i0][p0]  = (tok << 1);
        g_gate[i0][p0] = g0;
        int p1 = atomicAdd(&g_cnt[i1], 1);
        g_asg[i1][p1]  = (tok << 1) | 1;
        g_gate[i1][p1] = g1;
    }
}

// ---------------- aux loss ----------------
__global__ void aux_kernel(float* __restrict__ out_aux) {
    float s = 0.f;
#pragma unroll
    for (int e = 0; e < E_NUM; e++) {
        float load = (float)g_cnt[e] / (float)(N_TOK * 2);
        s += load * load;
    }
    *out_aux = 0.01f * (float)E_NUM * s;
}

// ---------------- GEMM1: h = silu(Xg @ w1[e]^T + b1[e]) ----------------
// C tile [BM tokens x BN h-cols], K = D_DIM. Both operands K-contiguous (NT gemm).
__global__ __launch_bounds__(NTHREADS) void gemm1_kernel(
    const float* __restrict__ x,
    const float* __restrict__ w1,
    const float* __restrict__ b1)
{
    const int e   = blockIdx.z;
    const int cnt = g_cnt[e];
    const int m0  = blockIdx.y * BM;
    if (m0 >= cnt) return;
    const int n0  = blockIdx.x * BN;

    __shared__ float As[BK * BM];
    __shared__ float Bs[BK * BN];
    __shared__ int   sAsg[BM];

    const int tid = threadIdx.x;
    if (tid < BM) {
        int r = m0 + tid;
        sAsg[tid] = (r < cnt) ? g_asg[e][r] : -1;
    }
    __syncthreads();

    const int innerRow = tid >> 1;   // 0..127
    const int innerCol = tid & 1;    // 0..1 (float4 column within BK=8)

    int aidA = sAsg[innerRow];
    int tokA = (aidA >= 0) ? (aidA >> 1) : 0;
    const float* aPtr = x  + (size_t)tokA * D_DIM + innerCol * 4;
    const float* bPtr = w1 + ((size_t)e * H_DIM + (size_t)(n0 + innerRow)) * D_DIM + innerCol * 4;

    const int threadCol = tid % (BN / TN);  // 0..15
    const int threadRow = tid / (BN / TN);  // 0..15

    float acc[TM][TN];
#pragma unroll
    for (int i = 0; i < TM; i++)
#pragma unroll
        for (int j = 0; j < TN; j++) acc[i][j] = 0.f;

    float regM[TM], regN[TN];

    for (int k0 = 0; k0 < D_DIM; k0 += BK) {
        float4 a4 = *(const float4*)(aPtr + k0);
        float4 b4 = *(const float4*)(bPtr + k0);
        As[(innerCol * 4 + 0) * BM + innerRow] = a4.x;
        As[(innerCol * 4 + 1) * BM + innerRow] = a4.y;
        As[(innerCol * 4 + 2) * BM + innerRow] = a4.z;
        As[(innerCol * 4 + 3) * BM + innerRow] = a4.w;
        Bs[(innerCol * 4 + 0) * BN + innerRow] = b4.x;
        Bs[(innerCol * 4 + 1) * BN + innerRow] = b4.y;
        Bs[(innerCol * 4 + 2) * BN + innerRow] = b4.z;
        Bs[(innerCol * 4 + 3) * BN + innerRow] = b4.w;
        __syncthreads();
#pragma unroll
        for (int kk = 0; kk < BK; kk++) {
#pragma unroll
            for (int i = 0; i < TM; i++) regM[i] = As[kk * BM + threadRow * TM + i];
#pragma unroll
            for (int j = 0; j < TN; j++) regN[j] = Bs[kk * BN + threadCol * TN + j];
#pragma unroll
            for (int i = 0; i < TM; i++)
#pragma unroll
                for (int j = 0; j < TN; j++)
                    acc[i][j] = fmaf(regM[i], regN[j], acc[i][j]);
        }
        __syncthreads();
    }

    // epilogue: +b1, silu, store to g_h[assignment]
#pragma unroll
    for (int i = 0; i < TM; i++) {
        int r   = threadRow * TM + i;
        int aid = sAsg[r];
        if (aid < 0) continue;
        float*       hrow = g_h + (size_t)aid * H_DIM + n0 + threadCol * TN;
        const float* brow = b1  + (size_t)e * H_DIM + n0 + threadCol * TN;
#pragma unroll
        for (int j = 0; j < TN; j++) {
            float v = acc[i][j] + brow[j];
            hrow[j] = v / (1.f + expf(-v));   // silu
        }
    }
}

// ---------------- GEMM2: y = Hg @ w2[e]^T + b2[e]; out[tok] += gate*y ----------------
__global__ __launch_bounds__(NTHREADS) void gemm2_kernel(
    const float* __restrict__ w2,
    const float* __restrict__ b2,
    float* __restrict__ out)
{
    const int e   = blockIdx.z;
    const int cnt = g_cnt[e];
    const int m0  = blockIdx.y * BM;
    if (m0 >= cnt) return;
    const int n0  = blockIdx.x * BN;

    __shared__ float As[BK * BM];
    __shared__ float Bs[BK * BN];
    __shared__ int   sAsg[BM];
    __shared__ float sGate[BM];

    const int tid = threadIdx.x;
    if (tid < BM) {
        int r = m0 + tid;
        sAsg[tid]  = (r < cnt) ? g_asg[e][r] : -1;
        sGate[tid] = (r < cnt) ? g_gate[e][r] : 0.f;
    }
    __syncthreads();

    const int innerRow = tid >> 1;
    const int innerCol = tid & 1;

    int aidA = sAsg[innerRow];
    int rowA = (aidA >= 0) ? aidA : 0;
    const float* aPtr = g_h + (size_t)rowA * H_DIM + innerCol * 4;
    const float* bPtr = w2  + ((size_t)e * D_DIM + (size_t)(n0 + innerRow)) * H_DIM + innerCol * 4;

    const int threadCol = tid % (BN / TN);
    const int threadRow = tid / (BN / TN);

    float acc[TM][TN];
#pragma unroll
    for (int i = 0; i < TM; i++)
#pragma unroll
        for (int j = 0; j < TN; j++) acc[i][j] = 0.f;

    float regM[TM], regN[TN];

    for (int k0 = 0; k0 < H_DIM; k0 += BK) {
        float4 a4 = *(const float4*)(aPtr + k0);
        float4 b4 = *(const float4*)(bPtr + k0);
        As[(innerCol * 4 + 0) * BM + innerRow] = a4.x;
        As[(innerCol * 4 + 1) * BM + innerRow] = a4.y;
        As[(innerCol * 4 + 2) * BM + innerRow] = a4.z;
        As[(innerCol * 4 + 3) * BM + innerRow] = a4.w;
        Bs[(innerCol * 4 + 0) * BN + innerRow] = b4.x;
        Bs[(innerCol * 4 + 1) * BN + innerRow] = b4.y;
        Bs[(innerCol * 4 + 2) * BN + innerRow] = b4.z;
        Bs[(innerCol * 4 + 3) * BN + innerRow] = b4.w;
        __syncthreads();
#pragma unroll
        for (int kk = 0; kk < BK; kk++) {
#pragma unroll
            for (int i = 0; i < TM; i++) regM[i] = As[kk * BM + threadRow * TM + i];
#pragma unroll
            for (int j = 0; j < TN; j++) regN[j] = Bs[kk * BN + threadCol * TN + j];
#pragma unroll
            for (int i = 0; i < TM; i++)
#pragma unroll
                for (int j = 0; j < TN; j++)
                    acc[i][j] = fmaf(regM[i], regN[j], acc[i][j]);
        }
        __syncthreads();
    }

    // epilogue: out[tok, d] += gate * (acc + b2)   (2 contributions per token -> commutative)
#pragma unroll
    for (int i = 0; i < TM; i++) {
        int r   = threadRow * TM + i;
        int aid = sAsg[r];
        if (aid < 0) continue;
        int tok = aid >> 1;
        float g = sGate[r];
        float*       orow = out + (size_t)tok * D_DIM + n0 + threadCol * TN;
        const float* brow = b2  + (size_t)e * D_DIM + n0 + threadCol * TN;
#pragma unroll
        for (int j = 0; j < TN; j++) {
            atomicAdd(&orow[j], g * (acc[i][j] + brow[j]));
        }
    }
}

// ---------------- launch ----------------
extern "C" void kernel_launch(void* const* d_in, const int* in_sizes, int n_in,
                              void* d_out, int out_size) {
    const float* x  = (const float*)d_in[0];
    const float* gw = (const float*)d_in[1];
    const float* w1 = (const float*)d_in[2];
    const float* b1 = (const float*)d_in[3];
    const float* w2 = (const float*)d_in[4];
    const float* b2 = (const float*)d_in[5];
    float* out = (float*)d_out;

    // zero the dense output region (poisoned 0xAA by harness)
    cudaMemsetAsync(out, 0, (size_t)N_TOK * D_DIM * sizeof(float), 0);

    init_kernel<<<1, 32>>>();
    gating_kernel<<<N_TOK / 8, 256>>>(x, gw);            // 8 warps/block, 1 warp/token
    aux_kernel<<<1, 1>>>(out + (out_size - 1));          // aux_loss is the last element

    dim3 g1(H_DIM / BN, N_TOK / BM, E_NUM);              // (16, 32, 8)
    gemm1_kernel<<<g1, NTHREADS>>>(x, w1, b1);

    dim3 g2(D_DIM / BN, N_TOK / BM, E_NUM);              // (8, 32, 8)
    gemm2_kernel<<<g2, NTHREADS>>>(w2, b2, out);
}

// round 3
// speedup vs baseline: 1.8112x; 1.8112x over previous
#include <cuda_runtime.h>
#include <cuda_bf16.h>
#include <math.h>
#include <stdint.h>

#define N_TOK 4096
#define D_DIM 1024
#define H_DIM 2048
#define E_NUM 8
#define NASG  (N_TOK * 2)
#define K3_1  (3 * D_DIM)   // 3072 : gemm1 extended K
#define K3_2  (3 * H_DIM)   // 6144 : gemm2 extended K

#define BM 128
#define BN 128
#define BKB 128             // bytes per row per k-chunk (64 bf16)
#define NSTAGE 3
#define TILE_BYTES (BM * BKB)            // 16384
#define STAGE_BYTES (2 * TILE_BYTES)     // A + B
#define SMEM_DYN (1024 + 2048 + NSTAGE * STAGE_BYTES)

// ---------------- device scratch ----------------
__device__ int   g_cnt[E_NUM];
__device__ int   g_asg[E_NUM][N_TOK];
__device__ float g_gate[E_NUM][N_TOK];

__device__ __align__(256) __nv_bfloat16 g_xs[(size_t)N_TOK * K3_1];           // [hi|hi|lo]
__device__ __align__(256) __nv_bfloat16 g_w1s[(size_t)E_NUM * H_DIM * K3_1];  // [hi|lo|hi]
__device__ __align__(256) __nv_bfloat16 g_w2s[(size_t)E_NUM * D_DIM * K3_2];  // [hi|lo|hi]
__device__ __align__(256) __nv_bfloat16 g_hs[(size_t)NASG * K3_2];            // [hi|hi|lo]

// ---------------- helpers ----------------
__device__ __forceinline__ uint32_t smem_u32(const void* p) {
    uint32_t a;
    asm("{ .reg .u64 t; cvta.to.shared.u64 t, %1; cvt.u32.u64 %0, t; }" : "=r"(a) : "l"(p));
    return a;
}
#define SW128(o) ((o) ^ (((o) >> 3) & 0x70))

#define CP16(dst, src) asm volatile("cp.async.cg.shared.global [%0], [%1], 16;" :: "r"(dst), "l"(src))
#define CP_COMMIT()    asm volatile("cp.async.commit_group;" ::: "memory")
#define CP_WAIT1()     asm volatile("cp.async.wait_group 1;" ::: "memory")
#define CP_WAIT0()     asm volatile("cp.async.wait_group 0;" ::: "memory")

#define LDSM4(r0, r1, r2, r3, addr)                                             \
    asm volatile("ldmatrix.sync.aligned.m8n8.x4.shared.b16 {%0,%1,%2,%3}, [%4];" \
        : "=r"(r0), "=r"(r1), "=r"(r2), "=r"(r3) : "r"(addr))

#define MMA16816(d, a0, a1, a2, a3, b0, b1)                                     \
    asm volatile("mma.sync.aligned.m16n8k16.row.col.f32.bf16.bf16.f32 "         \
        "{%0,%1,%2,%3}, {%4,%5,%6,%7}, {%8,%9}, {%0,%1,%2,%3};"                 \
        : "+f"((d)[0]), "+f"((d)[1]), "+f"((d)[2]), "+f"((d)[3])                \
        : "r"(a0), "r"(a1), "r"(a2), "r"(a3), "r"(b0), "r"(b1))

__device__ __forceinline__ void split2(float v, unsigned short& h, unsigned short& l) {
    __nv_bfloat16 hb = __float2bfloat16(v);
    __nv_bfloat16 lb = __float2bfloat16(v - __bfloat162float(hb));
    h = __bfloat16_as_ushort(hb);
    l = __bfloat16_as_ushort(lb);
}

// ---------------- small kernels ----------------
__global__ void init_kernel() {
    if (threadIdx.x < E_NUM) g_cnt[threadIdx.x] = 0;
}

__global__ void gating_kernel(const float* __restrict__ x, const float* __restrict__ gw) {
    int tok  = (blockIdx.x * blockDim.x + threadIdx.x) >> 5;
    int lane = threadIdx.x & 31;
    if (tok >= N_TOK) return;
    const float* xr = x + (size_t)tok * D_DIM;
    float acc[E_NUM];
#pragma unroll
    for (int e = 0; e < E_NUM; e++) acc[e] = 0.f;
    for (int d = lane; d < D_DIM; d += 32) {
        float xv = xr[d];
#pragma unroll
        for (int e = 0; e < E_NUM; e++)
            acc[e] = fmaf(xv, __ldg(gw + (size_t)e * D_DIM + d), acc[e]);
    }
#pragma unroll
    for (int e = 0; e < E_NUM; e++) {
#pragma unroll
        for (int off = 16; off > 0; off >>= 1)
            acc[e] += __shfl_xor_sync(0xffffffffu, acc[e], off);
    }
    if (lane == 0) {
        int i0 = 0; float v0 = acc[0];
#pragma unroll
        for (int e = 1; e < E_NUM; e++)
            if (acc[e] > v0) { v0 = acc[e]; i0 = e; }
        int i1 = -1; float v1 = -3.4e38f;
#pragma unroll
        for (int e = 0; e < E_NUM; e++)
            if (e != i0 && acc[e] > v1) { v1 = acc[e]; i1 = e; }
        float ex = expf(v1 - v0);
        float s  = 1.f + ex;
        int p0 = atomicAdd(&g_cnt[i0], 1);
        g_asg[i0][p0]  = (tok << 1);
        g_gate[i0][p0] = 1.f / s;
        int p1 = atomicAdd(&g_cnt[i1], 1);
        g_asg[i1][p1]  = (tok << 1) | 1;
        g_gate[i1][p1] = ex / s;
    }
}

__global__ void aux_kernel(float* __restrict__ out_aux) {
    float s = 0.f;
#pragma unroll
    for (int e = 0; e < E_NUM; e++) {
        float load = (float)g_cnt[e] / (float)(N_TOK * 2);
        s += load * load;
    }
    *out_aux = 0.01f * (float)E_NUM * s;
}

// x: [N,D] fp32 -> g_xs [N, 3D] = [hi | hi | lo]
__global__ void split_x_kernel(const float4* __restrict__ src) {
    int i = blockIdx.x * blockDim.x + threadIdx.x;
    if (i >= N_TOK * (D_DIM / 4)) return;
    int tok = i >> 8;             // D/4 = 256
    int d4  = (i & 255) * 4;
    float4 v = src[i];
    float f[4] = {v.x, v.y, v.z, v.w};
    unsigned short hs[4], ls[4];
#pragma unroll
    for (int k = 0; k < 4; k++) split2(f[k], hs[k], ls[k]);
    uint2 hi = make_uint2((uint32_t)hs[0] | ((uint32_t)hs[1] << 16),
                          (uint32_t)hs[2] | ((uint32_t)hs[3] << 16));
    uint2 lo = make_uint2((uint32_t)ls[0] | ((uint32_t)ls[1] << 16),
                          (uint32_t)ls[2] | ((uint32_t)ls[3] << 16));
    __nv_bfloat16* r = g_xs + (size_t)tok * K3_1 + d4;
    *(uint2*)r = hi;
    *(uint2*)(r + D_DIM) = hi;
    *(uint2*)(r + 2 * D_DIM) = lo;
}

// w: [rows, K] fp32 -> dst [rows, 3K] = [hi | lo | hi]; kshift = log2(K/4)
__global__ void split_w_kernel(const float4* __restrict__ src, __nv_bfloat16* __restrict__ dst,
                               int K, int kshift, int total4) {
    int i = blockIdx.x * blockDim.x + threadIdx.x;
    if (i >= total4) return;
    int row = i >> kshift;
    int d4  = (i & ((1 << kshift) - 1)) * 4;
    float4 v = src[i];
    float f[4] = {v.x, v.y, v.z, v.w};
    unsigned short hs[4], ls[4];
#pragma unroll
    for (int k = 0; k < 4; k++) split2(f[k], hs[k], ls[k]);
    uint2 hi = make_uint2((uint32_t)hs[0] | ((uint32_t)hs[1] << 16),
                          (uint32_t)hs[2] | ((uint32_t)hs[3] << 16));
    uint2 lo = make_uint2((uint32_t)ls[0] | ((uint32_t)ls[1] << 16),
                          (uint32_t)ls[2] | ((uint32_t)ls[3] << 16));
    __nv_bfloat16* r = dst + (size_t)row * (3 * K) + d4;
    *(uint2*)r = hi;
    *(uint2*)(r + K) = lo;
    *(uint2*)(r + 2 * K) = hi;
}

// ---------------- HMMA GEMM mainloop (shared pattern) ----------------
// Computes a BMxBN fp32 tile with A gathered rows, B contiguous rows, K-major bf16.
#define GEMM_MAINLOOP(KEXT, SRC_A_EXPR, SRC_B_EXPR)                                \
    const int C = (KEXT) / 64;                                                     \
    const int rowL  = tid >> 1;                                                    \
    const int cBase = (tid & 1) * 4;                                               \
    const char* srcA = SRC_A_EXPR;                                                 \
    const char* srcB = SRC_B_EXPR;                                                 \
    uint32_t dA[4], dB[4];                                                         \
    _Pragma("unroll")                                                              \
    for (int t = 0; t < 4; t++) {                                                  \
        uint32_t so = SW128((uint32_t)(rowL * 128 + (cBase + t) * 16));            \
        dA[t] = so; dB[t] = so + TILE_BYTES;                                       \
    }                                                                              \
    _Pragma("unroll")                                                              \
    for (int c = 0; c < 2; c++) {                                                  \
        uint32_t sb = ub + c * STAGE_BYTES;                                        \
        size_t ko = (size_t)c * 128;                                               \
        _Pragma("unroll")                                                          \
        for (int t = 0; t < 4; t++) {                                              \
            CP16(sb + dA[t], srcA + ko + t * 16);                                  \
            CP16(sb + dB[t], srcB + ko + t * 16);                                  \
        }                                                                          \
        CP_COMMIT();                                                               \
    }                                                                              \
    const int wm = (wid & 3) * 32;                                                 \
    const int wn = (wid >> 2) * 64;                                                \
    float acc[2][8][4];                                                            \
    _Pragma("unroll")                                                              \
    for (int i = 0; i < 2; i++)                                                    \
        _Pragma("unroll")                                                          \
        for (int j = 0; j < 8; j++)                                                \
            _Pragma("unroll")                                                      \
            for (int q = 0; q < 4; q++) acc[i][j][q] = 0.f;                        \
    for (int c = 0; c < C; c++) {                                                  \
        if (c >= C - 2) { CP_WAIT0(); } else { CP_WAIT1(); }                       \
        __syncthreads();                                                           \
        int cn = c + 2;                                                            \
        if (cn < C) {                                                              \
            uint32_t sb = ub + (cn % NSTAGE) * STAGE_BYTES;                        \
            size_t ko = (size_t)cn * 128;                                          \
            _Pragma("unroll")                                                      \
            for (int t = 0; t < 4; t++) {                                          \
                CP16(sb + dA[t], srcA + ko + t * 16);                              \
                CP16(sb + dB[t], srcB + ko + t * 16);                              \
            }                                                                      \
            CP_COMMIT();                                                           \
        }                                                                          \
        uint32_t sA = ub + (c % NSTAGE) * STAGE_BYTES;                             \
        uint32_t sB = sA + TILE_BYTES;                                             \
        _Pragma("unroll")                                                          \
        for (int kk = 0; kk < 4; kk++) {                                           \
            uint32_t a[2][4], b[4][4];                                             \
            _Pragma("unroll")                                                      \
            for (int mi = 0; mi < 2; mi++) {                                       \
                uint32_t off = (uint32_t)((wm + mi * 16 + (lane & 15)) * 128       \
                                          + kk * 32 + (lane >> 4) * 16);           \
                LDSM4(a[mi][0], a[mi][1], a[mi][2], a[mi][3], sA + SW128(off));    \
            }                                                                      \
            _Pragma("unroll")                                                      \
            for (int nq = 0; nq < 4; nq++) {                                       \
                uint32_t off = (uint32_t)((wn + nq * 16 + (lane & 15)) * 128       \
                                          + kk * 32 + (lane >> 4) * 16);           \
                LDSM4(b[nq][0], b[nq][1], b[nq][2], b[nq][3], sB + SW128(off));    \
            }                                                                      \
            _Pragma("unroll")                                                      \
            for (int mi = 0; mi < 2; mi++)                                         \
                _Pragma("unroll")                                                  \
                for (int nq = 0; nq < 4; nq++) {                                   \
                    MMA16816(acc[mi][nq * 2],     a[mi][0], a[mi][1], a[mi][2],    \
                             a[mi][3], b[nq][0], b[nq][2]);                        \
                    MMA16816(acc[mi][nq * 2 + 1], a[mi][0], a[mi][1], a[mi][2],    \
                             a[mi][3], b[nq][1], b[nq][3]);                        \
                }                                                                  \
        }                                                                          \
    }

// GEMM1: h_s[aid] = splitK( silu(x_s[tok] @ w1_s[e]^T + b1[e]) )
__global__ __launch_bounds__(256, 1) void gemm1_mma(const float* __restrict__ b1) {
    const int e   = blockIdx.z;
    const int cnt = g_cnt[e];
    const int m0  = blockIdx.x * BM;
    if (m0 >= cnt) return;
    const int n0  = blockIdx.y * BN;

    extern __shared__ char dsm[];
    char* base = (char*)(((uintptr_t)dsm + 1023) & ~(uintptr_t)1023);
    int* sAsg = (int*)base;
    uint32_t ub = smem_u32(base) + 3072;

    const int tid = threadIdx.x, wid = tid >> 5, lane = tid & 31;
    if (tid < BM) {
        int r = m0 + tid;
        sAsg[tid] = (r < cnt) ? g_asg[e][r] : -1;
    }
    __syncthreads();

    int aidL = sAsg[tid >> 1];
    int tokL = (aidL >= 0) ? (aidL >> 1) : 0;

    GEMM_MAINLOOP(K3_1,
        (const char*)g_xs  + ((size_t)tokL * K3_1 + (size_t)(tid & 1) * 32) * 2,
        (const char*)g_w1s + (((size_t)e * H_DIM + n0 + (tid >> 1)) * K3_1 + (size_t)(tid & 1) * 32) * 2)

    // epilogue
    const float* b1e = b1 + (size_t)e * H_DIM + n0;
    float bias[8][2];
#pragma unroll
    for (int ni = 0; ni < 8; ni++) {
        int cb = wn + ni * 8 + (lane & 3) * 2;
        bias[ni][0] = __ldg(b1e + cb);
        bias[ni][1] = __ldg(b1e + cb + 1);
    }
#pragma unroll
    for (int mi = 0; mi < 2; mi++) {
#pragma unroll
        for (int h = 0; h < 2; h++) {
            int row = wm + mi * 16 + (lane >> 2) + h * 8;
            int aid = sAsg[row];
            if (aid < 0) continue;
            __nv_bfloat16* hrow = g_hs + (size_t)aid * K3_2;
#pragma unroll
            for (int ni = 0; ni < 8; ni++) {
                int cb = wn + ni * 8 + (lane & 3) * 2;
                float v0 = acc[mi][ni][h * 2]     + bias[ni][0];
                float v1 = acc[mi][ni][h * 2 + 1] + bias[ni][1];
                v0 = v0 / (1.f + expf(-v0));
                v1 = v1 / (1.f + expf(-v1));
                unsigned short h0, l0, h1, l1;
                split2(v0, h0, l0);
                split2(v1, h1, l1);
                uint32_t hp = (uint32_t)h0 | ((uint32_t)h1 << 16);
                uint32_t lp = (uint32_t)l0 | ((uint32_t)l1 << 16);
                int g = n0 + cb;
                *(uint32_t*)(hrow + g) = hp;
                *(uint32_t*)(hrow + g + H_DIM) = hp;
                *(uint32_t*)(hrow + g + 2 * H_DIM) = lp;
            }
        }
    }
}

// GEMM2: out[tok] += gate * ( h_s[aid] @ w2_s[e]^T + b2[e] )
__global__ __launch_bounds__(256, 1) void gemm2_mma(const float* __restrict__ b2,
                                                    float* __restrict__ out) {
    const int e   = blockIdx.z;
    const int cnt = g_cnt[e];
    const int m0  = blockIdx.x * BM;
    if (m0 >= cnt) return;
    const int n0  = blockIdx.y * BN;

    extern __shared__ char dsm[];
    char* base = (char*)(((uintptr_t)dsm + 1023) & ~(uintptr_t)1023);
    int*   sAsg  = (int*)base;
    float* sGate = (float*)(base + 512);
    uint32_t ub = smem_u32(base) + 3072;

    const int tid = threadIdx.x, wid = tid >> 5, lane = tid & 31;
    if (tid < BM) {
        int r = m0 + tid;
        sAsg[tid]  = (r < cnt) ? g_asg[e][r] : -1;
        sGate[tid] = (r < cnt) ? g_gate[e][r] : 0.f;
    }
    __syncthreads();

    int aidL = sAsg[tid >> 1];
    int arwL = (aidL >= 0) ? aidL : 0;

    GEMM_MAINLOOP(K3_2,
        (const char*)g_hs  + ((size_t)arwL * K3_2 + (size_t)(tid & 1) * 32) * 2,
        (const char*)g_w2s + (((size_t)e * D_DIM + n0 + (tid >> 1)) * K3_2 + (size_t)(tid & 1) * 32) * 2)

    // epilogue
    const float* b2e = b2 + (size_t)e * D_DIM + n0;
    float bias[8][2];
#pragma unroll
    for (int ni = 0; ni < 8; ni++) {
        int cb = wn + ni * 8 + (lane & 3) * 2;
        bias[ni][0] = __ldg(b2e + cb);
        bias[ni][1] = __ldg(b2e + cb + 1);
    }
#pragma unroll
    for (int mi = 0; mi < 2; mi++) {
#pragma unroll
        for (int h = 0; h < 2; h++) {
            int row = wm + mi * 16 + (lane >> 2) + h * 8;
            int aid = sAsg[row];
            if (aid < 0) continue;
            float gte = sGate[row];
            float* orow = out + (size_t)(aid >> 1) * D_DIM + n0;
#pragma unroll
            for (int ni = 0; ni < 8; ni++) {
                int cb = wn + ni * 8 + (lane & 3) * 2;
                atomicAdd(orow + cb,     gte * (acc[mi][ni][h * 2]     + bias[ni][0]));
                atomicAdd(orow + cb + 1, gte * (acc[mi][ni][h * 2 + 1] + bias[ni][1]));
            }
        }
    }
}

// ---------------- launch ----------------
extern "C" void kernel_launch(void* const* d_in, const int* in_sizes, int n_in,
                              void* d_out, int out_size) {
    const float* x  = (const float*)d_in[0];
    const float* gw = (const float*)d_in[1];
    const float* w1 = (const float*)d_in[2];
    const float* b1 = (const float*)d_in[3];
    const float* w2 = (const float*)d_in[4];
    const float* b2 = (const float*)d_in[5];
    float* out = (float*)d_out;

    cudaFuncSetAttribute(gemm1_mma, cudaFuncAttributeMaxDynamicSharedMemorySize, SMEM_DYN);
    cudaFuncSetAttribute(gemm2_mma, cudaFuncAttributeMaxDynamicSharedMemorySize, SMEM_DYN);

    cudaMemsetAsync(out, 0, (size_t)N_TOK * D_DIM * sizeof(float), 0);

    init_kernel<<<1, 32>>>();
    gating_kernel<<<N_TOK / 8, 256>>>(x, gw);
    aux_kernel<<<1, 1>>>(out + (out_size - 1));

    __nv_bfloat16 *w1s, *w2s;
    cudaGetSymbolAddress((void**)&w1s, g_w1s);
    cudaGetSymbolAddress((void**)&w2s, g_w2s);

    int nx4  = N_TOK * (D_DIM / 4);
    int nw14 = E_NUM * H_DIM * (D_DIM / 4);
    int nw24 = E_NUM * D_DIM * (H_DIM / 4);
    split_x_kernel<<<(nx4 + 255) / 256, 256>>>((const float4*)x);
    split_w_kernel<<<(nw14 + 255) / 256, 256>>>((const float4*)w1, w1s, D_DIM, 8, nw14);
    split_w_kernel<<<(nw24 + 255) / 256, 256>>>((const float4*)w2, w2s, H_DIM, 9, nw24);

    dim3 g1(N_TOK / BM, H_DIM / BN, E_NUM);   // (32, 16, 8), m fastest
    gemm1_mma<<<g1, 256, SMEM_DYN>>>(b1);

    dim3 g2(N_TOK / BM, D_DIM / BN, E_NUM);   // (32, 8, 8)
    gemm2_mma<<<g2, 256, SMEM_DYN>>>(b2, out);
}

// round 4
// speedup vs baseline: 2.8997x; 1.6010x over previous
#include <cuda_runtime.h>
#include <cuda_fp16.h>
#include <math.h>
#include <stdint.h>

#define N_TOK 4096
#define D_DIM 1024
#define H_DIM 2048
#define E_NUM 8
#define NASG  (N_TOK * 2)

#define BM 128
#define BN 128
#define NSTAGE 3
#define TILE_BYTES (BM * 128)                 // 16384 per operand tile
#define STAGE_BYTES (3 * TILE_BYTES)          // A_hi + A_lo + B
#define SMEM_DYN (1024 + 3072 + NSTAGE * STAGE_BYTES)

// ---------------- device scratch ----------------
__device__ int   g_cnt[E_NUM];
__device__ int   g_asg[E_NUM][N_TOK];
__device__ float g_gate[E_NUM][N_TOK];

__device__ __align__(256) __half g_xh[(size_t)N_TOK * D_DIM];
__device__ __align__(256) __half g_xl[(size_t)N_TOK * D_DIM];
__device__ __align__(256) __half g_w1h[(size_t)E_NUM * H_DIM * D_DIM];
__device__ __align__(256) __half g_w2h[(size_t)E_NUM * D_DIM * H_DIM];
__device__ __align__(256) __half g_hh[(size_t)NASG * H_DIM];
__device__ __align__(256) __half g_hl[(size_t)NASG * H_DIM];

// ---------------- helpers ----------------
__device__ __forceinline__ uint32_t smem_u32(const void* p) {
    uint32_t a;
    asm("{ .reg .u64 t; cvta.to.shared.u64 t, %1; cvt.u32.u64 %0, t; }" : "=r"(a) : "l"(p));
    return a;
}
#define SW128(o) ((o) ^ (((o) >> 3) & 0x70))

#define CP16(dst, src) asm volatile("cp.async.cg.shared.global [%0], [%1], 16;" :: "r"(dst), "l"(src))
#define CP_COMMIT()    asm volatile("cp.async.commit_group;" ::: "memory")
#define CP_WAIT1()     asm volatile("cp.async.wait_group 1;" ::: "memory")
#define CP_WAIT0()     asm volatile("cp.async.wait_group 0;" ::: "memory")

#define LDSM4(r0, r1, r2, r3, addr)                                             \
    asm volatile("ldmatrix.sync.aligned.m8n8.x4.shared.b16 {%0,%1,%2,%3}, [%4];" \
        : "=r"(r0), "=r"(r1), "=r"(r2), "=r"(r3) : "r"(addr))

#define MMA16816(d, a0, a1, a2, a3, b0, b1)                                     \
    asm volatile("mma.sync.aligned.m16n8k16.row.col.f32.f16.f16.f32 "           \
        "{%0,%1,%2,%3}, {%4,%5,%6,%7}, {%8,%9}, {%0,%1,%2,%3};"                 \
        : "+f"((d)[0]), "+f"((d)[1]), "+f"((d)[2]), "+f"((d)[3])                \
        : "r"(a0), "r"(a1), "r"(a2), "r"(a3), "r"(b0), "r"(b1))

__device__ __forceinline__ void split2h(float v, unsigned short& h, unsigned short& l) {
    __half hb = __float2half(v);
    __half lb = __float2half(v - __half2float(hb));
    h = __half_as_ushort(hb);
    l = __half_as_ushort(lb);
}

// ---------------- small kernels ----------------
__global__ void init_kernel() {
    if (threadIdx.x < E_NUM) g_cnt[threadIdx.x] = 0;
}

__global__ void gating_kernel(const float* __restrict__ x, const float* __restrict__ gw) {
    int tok  = (blockIdx.x * blockDim.x + threadIdx.x) >> 5;
    int lane = threadIdx.x & 31;
    if (tok >= N_TOK) return;
    const float* xr = x + (size_t)tok * D_DIM;
    float acc[E_NUM];
#pragma unroll
    for (int e = 0; e < E_NUM; e++) acc[e] = 0.f;
    for (int d = lane; d < D_DIM; d += 32) {
        float xv = xr[d];
#pragma unroll
        for (int e = 0; e < E_NUM; e++)
            acc[e] = fmaf(xv, __ldg(gw + (size_t)e * D_DIM + d), acc[e]);
    }
#pragma unroll
    for (int e = 0; e < E_NUM; e++) {
#pragma unroll
        for (int off = 16; off > 0; off >>= 1)
            acc[e] += __shfl_xor_sync(0xffffffffu, acc[e], off);
    }
    if (lane == 0) {
        int i0 = 0; float v0 = acc[0];
#pragma unroll
        for (int e = 1; e < E_NUM; e++)
            if (acc[e] > v0) { v0 = acc[e]; i0 = e; }
        int i1 = -1; float v1 = -3.4e38f;
#pragma unroll
        for (int e = 0; e < E_NUM; e++)
            if (e != i0 && acc[e] > v1) { v1 = acc[e]; i1 = e; }
        float ex = expf(v1 - v0);
        float s  = 1.f + ex;
        int p0 = atomicAdd(&g_cnt[i0], 1);
        g_asg[i0][p0]  = (tok << 1);
        g_gate[i0][p0] = 1.f / s;
        int p1 = atomicAdd(&g_cnt[i1], 1);
        g_asg[i1][p1]  = (tok << 1) | 1;
        g_gate[i1][p1] = ex / s;
    }
}

__global__ void aux_kernel(float* __restrict__ out_aux) {
    float s = 0.f;
#pragma unroll
    for (int e = 0; e < E_NUM; e++) {
        float load = (float)g_cnt[e] / (float)(N_TOK * 2);
        s += load * load;
    }
    *out_aux = 0.01f * (float)E_NUM * s;
}

// one kernel: x -> (hi, lo) fp16; w1, w2 -> hi fp16
#define NX4  (N_TOK * D_DIM / 4)
#define NW14 (E_NUM * H_DIM * D_DIM / 4)
#define NW24 (E_NUM * D_DIM * H_DIM / 4)
__global__ void split_all_kernel(const float4* __restrict__ x,
                                 const float4* __restrict__ w1,
                                 const float4* __restrict__ w2) {
    int i = blockIdx.x * blockDim.x + threadIdx.x;
    float4 v;
    if (i < NX4) {
        v = x[i];
        unsigned short hs[4], ls[4];
#pragma unroll
        for (int k = 0; k < 4; k++) split2h(((const float*)&v)[k], hs[k], ls[k]);
        ((uint2*)g_xh)[i] = make_uint2((uint32_t)hs[0] | ((uint32_t)hs[1] << 16),
                                       (uint32_t)hs[2] | ((uint32_t)hs[3] << 16));
        ((uint2*)g_xl)[i] = make_uint2((uint32_t)ls[0] | ((uint32_t)ls[1] << 16),
                                       (uint32_t)ls[2] | ((uint32_t)ls[3] << 16));
    } else if (i < NX4 + NW14) {
        int j = i - NX4;
        v = w1[j];
        unsigned short hs[4], ls[4];
#pragma unroll
        for (int k = 0; k < 4; k++) split2h(((const float*)&v)[k], hs[k], ls[k]);
        ((uint2*)g_w1h)[j] = make_uint2((uint32_t)hs[0] | ((uint32_t)hs[1] << 16),
                                        (uint32_t)hs[2] | ((uint32_t)hs[3] << 16));
    } else if (i < NX4 + NW14 + NW24) {
        int j = i - NX4 - NW14;
        v = w2[j];
        unsigned short hs[4], ls[4];
#pragma unroll
        for (int k = 0; k < 4; k++) split2h(((const float*)&v)[k], hs[k], ls[k]);
        ((uint2*)g_w2h)[j] = make_uint2((uint32_t)hs[0] | ((uint32_t)hs[1] << 16),
                                        (uint32_t)hs[2] | ((uint32_t)hs[3] << 16));
    }
}

// ---------------- HMMA mainloop: acc += (Ahi + Alo) @ B^T over K ----------------
// per stage: Ahi tile (16KB) | Alo tile (16KB) | B tile (16KB)
#define GEMM_MAINLOOP(KDIM, SRC_AH, SRC_AL, SRC_B)                                 \
    const int C = (KDIM) / 64;                                                     \
    const int rowL  = tid >> 1;                                                    \
    const int cBase = (tid & 1) * 4;                                               \
    const char* srcAh = SRC_AH;                                                    \
    const char* srcAl = SRC_AL;                                                    \
    const char* srcB  = SRC_B;                                                     \
    uint32_t dsto[4];                                                              \
    _Pragma("unroll")                                                              \
    for (int t = 0; t < 4; t++)                                                    \
        dsto[t] = SW128((uint32_t)(rowL * 128 + (cBase + t) * 16));                \
    _Pragma("unroll")                                                              \
    for (int c = 0; c < 2; c++) {                                                  \
        uint32_t sb = ub + c * STAGE_BYTES;                                        \
        size_t ko = (size_t)c * 128;                                               \
        _Pragma("unroll")                                                          \
        for (int t = 0; t < 4; t++) {                                              \
            CP16(sb + dsto[t],                  srcAh + ko + t * 16);              \
            CP16(sb + TILE_BYTES + dsto[t],     srcAl + ko + t * 16);              \
            CP16(sb + 2 * TILE_BYTES + dsto[t], srcB  + ko + t * 16);              \
        }                                                                          \
        CP_COMMIT();                                                               \
    }                                                                              \
    const int wm = (wid & 3) * 32;                                                 \
    const int wn = (wid >> 2) * 64;                                                \
    float acc[2][8][4];                                                            \
    _Pragma("unroll")                                                              \
    for (int i = 0; i < 2; i++)                                                    \
        _Pragma("unroll")                                                          \
        for (int j = 0; j < 8; j++)                                                \
            _Pragma("unroll")                                                      \
            for (int q = 0; q < 4; q++) acc[i][j][q] = 0.f;                        \
    for (int c = 0; c < C; c++) {                                                  \
        if (c >= C - 2) { CP_WAIT0(); } else { CP_WAIT1(); }                       \
        __syncthreads();                                                           \
        int cn = c + 2;                                                            \
        if (cn < C) {                                                              \
            uint32_t sb = ub + (cn % NSTAGE) * STAGE_BYTES;                        \
            size_t ko = (size_t)cn * 128;                                          \
            _Pragma("unroll")                                                      \
            for (int t = 0; t < 4; t++) {                                          \
                CP16(sb + dsto[t],                  srcAh + ko + t * 16);          \
                CP16(sb + TILE_BYTES + dsto[t],     srcAl + ko + t * 16);          \
                CP16(sb + 2 * TILE_BYTES + dsto[t], srcB  + ko + t * 16);          \
            }                                                                      \
            CP_COMMIT();                                                           \
        }                                                                          \
        uint32_t sAh = ub + (c % NSTAGE) * STAGE_BYTES;                            \
        uint32_t sAl = sAh + TILE_BYTES;                                           \
        uint32_t sB  = sAh + 2 * TILE_BYTES;                                       \
        _Pragma("unroll")                                                          \
        for (int kk = 0; kk < 4; kk++) {                                           \
            uint32_t ah[2][4], al[2][4], b[4][4];                                  \
            _Pragma("unroll")                                                      \
            for (int mi = 0; mi < 2; mi++) {                                       \
                uint32_t off = (uint32_t)((wm + mi * 16 + (lane & 15)) * 128       \
                                          + kk * 32 + (lane >> 4) * 16);           \
                uint32_t so = SW128(off);                                          \
                LDSM4(ah[mi][0], ah[mi][1], ah[mi][2], ah[mi][3], sAh + so);       \
                LDSM4(al[mi][0], al[mi][1], al[mi][2], al[mi][3], sAl + so);       \
            }                                                                      \
            _Pragma("unroll")                                                      \
            for (int nq = 0; nq < 4; nq++) {                                       \
                uint32_t off = (uint32_t)((wn + nq * 16 + (lane & 15)) * 128       \
                                          + kk * 32 + (lane >> 4) * 16);           \
                LDSM4(b[nq][0], b[nq][1], b[nq][2], b[nq][3], sB + SW128(off));    \
            }                                                                      \
            _Pragma("unroll")                                                      \
            for (int mi = 0; mi < 2; mi++)                                         \
                _Pragma("unroll")                                                  \
                for (int nq = 0; nq < 4; nq++) {                                   \
                    MMA16816(acc[mi][nq * 2],     ah[mi][0], ah[mi][1], ah[mi][2], \
                             ah[mi][3], b[nq][0], b[nq][2]);                       \
                    MMA16816(acc[mi][nq * 2 + 1], ah[mi][0], ah[mi][1], ah[mi][2], \
                             ah[mi][3], b[nq][1], b[nq][3]);                       \
                    MMA16816(acc[mi][nq * 2],     al[mi][0], al[mi][1], al[mi][2], \
                             al[mi][3], b[nq][0], b[nq][2]);                       \
                    MMA16816(acc[mi][nq * 2 + 1], al[mi][0], al[mi][1], al[mi][2], \
                             al[mi][3], b[nq][1], b[nq][3]);                       \
                }                                                                  \
        }                                                                          \
    }

// GEMM1: h[aid] = silu(x[tok] @ w1[e]^T + b1[e]) -> fp16 hi/lo
__global__ __launch_bounds__(256, 1) void gemm1_mma(const float* __restrict__ b1) {
    const int e   = blockIdx.z;
    const int cnt = g_cnt[e];
    const int m0  = blockIdx.x * BM;
    if (m0 >= cnt) return;
    const int n0  = blockIdx.y * BN;

    extern __shared__ char dsm[];
    char* base = (char*)(((uintptr_t)dsm + 1023) & ~(uintptr_t)1023);
    int* sAsg = (int*)base;
    uint32_t ub = smem_u32(base) + 3072;

    const int tid = threadIdx.x, wid = tid >> 5, lane = tid & 31;
    if (tid < BM) {
        int r = m0 + tid;
        sAsg[tid] = (r < cnt) ? g_asg[e][r] : -1;
    }
    __syncthreads();

    int aidL = sAsg[tid >> 1];
    int tokL = (aidL >= 0) ? (aidL >> 1) : 0;
    size_t aoff = ((size_t)tokL * D_DIM + (size_t)(tid & 1) * 32) * 2;
    size_t boff = (((size_t)e * H_DIM + n0 + (tid >> 1)) * D_DIM + (size_t)(tid & 1) * 32) * 2;

    GEMM_MAINLOOP(D_DIM,
        (const char*)g_xh + aoff,
        (const char*)g_xl + aoff,
        (const char*)g_w1h + boff)

    const float* b1e = b1 + (size_t)e * H_DIM + n0;
    float bias[8][2];
#pragma unroll
    for (int ni = 0; ni < 8; ni++) {
        int cb = wn + ni * 8 + (lane & 3) * 2;
        bias[ni][0] = __ldg(b1e + cb);
        bias[ni][1] = __ldg(b1e + cb + 1);
    }
#pragma unroll
    for (int mi = 0; mi < 2; mi++) {
#pragma unroll
        for (int h = 0; h < 2; h++) {
            int row = wm + mi * 16 + (lane >> 2) + h * 8;
            int aid = sAsg[row];
            if (aid < 0) continue;
            __half* hh = g_hh + (size_t)aid * H_DIM + n0;
            __half* hl = g_hl + (size_t)aid * H_DIM + n0;
#pragma unroll
            for (int ni = 0; ni < 8; ni++) {
                int cb = wn + ni * 8 + (lane & 3) * 2;
                float v0 = acc[mi][ni][h * 2]     + bias[ni][0];
                float v1 = acc[mi][ni][h * 2 + 1] + bias[ni][1];
                v0 = v0 / (1.f + __expf(-v0));
                v1 = v1 / (1.f + __expf(-v1));
                unsigned short h0, l0, h1, l1;
                split2h(v0, h0, l0);
                split2h(v1, h1, l1);
                *(uint32_t*)(hh + cb) = (uint32_t)h0 | ((uint32_t)h1 << 16);
                *(uint32_t*)(hl + cb) = (uint32_t)l0 | ((uint32_t)l1 << 16);
            }
        }
    }
}

// GEMM2: out[tok] += gate * ( h[aid] @ w2[e]^T + b2[e] )
__global__ __launch_bounds__(256, 1) void gemm2_mma(const float* __restrict__ b2,
                                                    float* __restrict__ out) {
    const int e   = blockIdx.z;
    const int cnt = g_cnt[e];
    const int m0  = blockIdx.x * BM;
    if (m0 >= cnt) return;
    const int n0  = blockIdx.y * BN;

    extern __shared__ char dsm[];
    char* base = (char*)(((uintptr_t)dsm + 1023) & ~(uintptr_t)1023);
    int*   sAsg  = (int*)base;
    float* sGate = (float*)(base + 512);
    uint32_t ub = smem_u32(base) + 3072;

    const int tid = threadIdx.x, wid = tid >> 5, lane = tid & 31;
    if (tid < BM) {
        int r = m0 + tid;
        sAsg[tid]  = (r < cnt) ? g_asg[e][r] : -1;
        sGate[tid] = (r < cnt) ? g_gate[e][r] : 0.f;
    }
    __syncthreads();

    int aidL = sAsg[tid >> 1];
    int arwL = (aidL >= 0) ? aidL : 0;
    size_t aoff = ((size_t)arwL * H_DIM + (size_t)(tid & 1) * 32) * 2;
    size_t boff = (((size_t)e * D_DIM + n0 + (tid >> 1)) * H_DIM + (size_t)(tid & 1) * 32) * 2;

    GEMM_MAINLOOP(H_DIM,
        (const char*)g_hh + aoff,
        (const char*)g_hl + aoff,
        (const char*)g_w2h + boff)

    const float* b2e = b2 + (size_t)e * D_DIM + n0;
    float bias[8][2];
#pragma unroll
    for (int ni = 0; ni < 8; ni++) {
        int cb = wn + ni * 8 + (lane & 3) * 2;
        bias[ni][0] = __ldg(b2e + cb);
        bias[ni][1] = __ldg(b2e + cb + 1);
    }
#pragma unroll
    for (int mi = 0; mi < 2; mi++) {
#pragma unroll
        for (int h = 0; h < 2; h++) {
            int row = wm + mi * 16 + (lane >> 2) + h * 8;
            int aid = sAsg[row];
            if (aid < 0) continue;
            float gte = sGate[row];
            float* orow = out + (size_t)(aid >> 1) * D_DIM + n0;
#pragma unroll
            for (int ni = 0; ni < 8; ni++) {
                int cb = wn + ni * 8 + (lane & 3) * 2;
                atomicAdd(orow + cb,     gte * (acc[mi][ni][h * 2]     + bias[ni][0]));
                atomicAdd(orow + cb + 1, gte * (acc[mi][ni][h * 2 + 1] + bias[ni][1]));
            }
        }
    }
}

// ---------------- launch ----------------
extern "C" void kernel_launch(void* const* d_in, const int* in_sizes, int n_in,
                              void* d_out, int out_size) {
    const float* x  = (const float*)d_in[0];
    const float* gw = (const float*)d_in[1];
    const float* w1 = (const float*)d_in[2];
    const float* b1 = (const float*)d_in[3];
    const float* w2 = (const float*)d_in[4];
    const float* b2 = (const float*)d_in[5];
    float* out = (float*)d_out;

    cudaFuncSetAttribute(gemm1_mma, cudaFuncAttributeMaxDynamicSharedMemorySize, SMEM_DYN);
    cudaFuncSetAttribute(gemm2_mma, cudaFuncAttributeMaxDynamicSharedMemorySize, SMEM_DYN);

    cudaMemsetAsync(out, 0, (size_t)N_TOK * D_DIM * sizeof(float), 0);

    init_kernel<<<1, 32>>>();
    gating_kernel<<<N_TOK / 8, 256>>>(x, gw);

    int total4 = NX4 + NW14 + NW24;
    split_all_kernel<<<(total4 + 255) / 256, 256>>>((const float4*)x, (const float4*)w1,
                                                    (const float4*)w2);

    // gemm1 placed 5th so the ncu -s5 window captures it
    dim3 g1(N_TOK / BM, H_DIM / BN, E_NUM);   // (32, 16, 8)
    gemm1_mma<<<g1, 256, SMEM_DYN>>>(b1);

    aux_kernel<<<1, 1>>>(out + (out_size - 1));

    dim3 g2(N_TOK / BM, D_DIM / BN, E_NUM);   // (32, 8, 8)
    gemm2_mma<<<g2, 256, SMEM_DYN>>>(b2, out);
}

// round 5
// speedup vs baseline: 5.1933x; 1.7910x over previous
#include <cuda_runtime.h>
#include <cuda_fp16.h>
#include <math.h>
#include <stdint.h>

#define N_TOK 4096
#define D_DIM 1024
#define H_DIM 2048
#define E_NUM 8
#define NASG  (N_TOK * 2)

#define BM 128
#define BN 128
#define NSTAGE 3
#define TILE_BYTES (BM * 128)                 // 16384 per operand tile
#define STAGE_BYTES (2 * TILE_BYTES)          // A + B
#define SMEM_DYN (1024 + 3072 + NSTAGE * STAGE_BYTES)   // ~100KB -> 2 CTAs/SM

// ---------------- device scratch ----------------
__device__ int   g_cnt[E_NUM];
__device__ int   g_asg[E_NUM][N_TOK];
__device__ float g_gate[E_NUM][N_TOK];

__device__ __align__(256) __half g_xh[(size_t)N_TOK * D_DIM];
__device__ __align__(256) __half g_w1h[(size_t)E_NUM * H_DIM * D_DIM];
__device__ __align__(256) __half g_w2h[(size_t)E_NUM * D_DIM * H_DIM];
__device__ __align__(256) __half g_hh[(size_t)NASG * H_DIM];

// ---------------- helpers ----------------
__device__ __forceinline__ uint32_t smem_u32(const void* p) {
    uint32_t a;
    asm("{ .reg .u64 t; cvta.to.shared.u64 t, %1; cvt.u32.u64 %0, t; }" : "=r"(a) : "l"(p));
    return a;
}
#define SW128(o) ((o) ^ (((o) >> 3) & 0x70))

#define CP16(dst, src) asm volatile("cp.async.cg.shared.global [%0], [%1], 16;" :: "r"(dst), "l"(src))
#define CP_COMMIT()    asm volatile("cp.async.commit_group;" ::: "memory")
#define CP_WAIT1()     asm volatile("cp.async.wait_group 1;" ::: "memory")
#define CP_WAIT0()     asm volatile("cp.async.wait_group 0;" ::: "memory")

#define LDSM4(r0, r1, r2, r3, addr)                                             \
    asm volatile("ldmatrix.sync.aligned.m8n8.x4.shared.b16 {%0,%1,%2,%3}, [%4];" \
        : "=r"(r0), "=r"(r1), "=r"(r2), "=r"(r3) : "r"(addr))

#define MMA16816(d, a0, a1, a2, a3, b0, b1)                                     \
    asm volatile("mma.sync.aligned.m16n8k16.row.col.f32.f16.f16.f32 "           \
        "{%0,%1,%2,%3}, {%4,%5,%6,%7}, {%8,%9}, {%0,%1,%2,%3};"                 \
        : "+f"((d)[0]), "+f"((d)[1]), "+f"((d)[2]), "+f"((d)[3])                \
        : "r"(a0), "r"(a1), "r"(a2), "r"(a3), "r"(b0), "r"(b1))

// ---------------- small kernels ----------------
__global__ void init_kernel() {
    if (threadIdx.x < E_NUM) g_cnt[threadIdx.x] = 0;
}

__global__ void gating_kernel(const float* __restrict__ x, const float* __restrict__ gw) {
    int tok  = (blockIdx.x * blockDim.x + threadIdx.x) >> 5;
    int lane = threadIdx.x & 31;
    if (tok >= N_TOK) return;
    const float* xr = x + (size_t)tok * D_DIM;
    float acc[E_NUM];
#pragma unroll
    for (int e = 0; e < E_NUM; e++) acc[e] = 0.f;
    for (int d = lane; d < D_DIM; d += 32) {
        float xv = xr[d];
#pragma unroll
        for (int e = 0; e < E_NUM; e++)
            acc[e] = fmaf(xv, __ldg(gw + (size_t)e * D_DIM + d), acc[e]);
    }
#pragma unroll
    for (int e = 0; e < E_NUM; e++) {
#pragma unroll
        for (int off = 16; off > 0; off >>= 1)
            acc[e] += __shfl_xor_sync(0xffffffffu, acc[e], off);
    }
    if (lane == 0) {
        int i0 = 0; float v0 = acc[0];
#pragma unroll
        for (int e = 1; e < E_NUM; e++)
            if (acc[e] > v0) { v0 = acc[e]; i0 = e; }
        int i1 = -1; float v1 = -3.4e38f;
#pragma unroll
        for (int e = 0; e < E_NUM; e++)
            if (e != i0 && acc[e] > v1) { v1 = acc[e]; i1 = e; }
        float ex = expf(v1 - v0);
        float s  = 1.f + ex;
        int p0 = atomicAdd(&g_cnt[i0], 1);
        g_asg[i0][p0]  = (tok << 1);
        g_gate[i0][p0] = 1.f / s;
        int p1 = atomicAdd(&g_cnt[i1], 1);
        g_asg[i1][p1]  = (tok << 1) | 1;
        g_gate[i1][p1] = ex / s;
    }
}

__global__ void aux_kernel(float* __restrict__ out_aux) {
    float s = 0.f;
#pragma unroll
    for (int e = 0; e < E_NUM; e++) {
        float load = (float)g_cnt[e] / (float)(N_TOK * 2);
        s += load * load;
    }
    *out_aux = 0.01f * (float)E_NUM * s;
}

// convert x, w1, w2 to fp16 in one pass
#define NX4  (N_TOK * D_DIM / 4)
#define NW14 (E_NUM * H_DIM * D_DIM / 4)
#define NW24 (E_NUM * D_DIM * H_DIM / 4)
__global__ void split_all_kernel(const float4* __restrict__ x,
                                 const float4* __restrict__ w1,
                                 const float4* __restrict__ w2) {
    int i = blockIdx.x * blockDim.x + threadIdx.x;
    const float4* src;
    uint2* dst;
    int j;
    if (i < NX4)                  { src = x;  j = i;               dst = (uint2*)g_xh; }
    else if (i < NX4 + NW14)      { src = w1; j = i - NX4;         dst = (uint2*)g_w1h; }
    else if (i < NX4 + NW14 + NW24){ src = w2; j = i - NX4 - NW14; dst = (uint2*)g_w2h; }
    else return;
    float4 v = src[j];
    __half2 lo = __floats2half2_rn(v.x, v.y);
    __half2 hi = __floats2half2_rn(v.z, v.w);
    dst[j] = make_uint2(*(uint32_t*)&lo, *(uint32_t*)&hi);
}

// ---------------- HMMA mainloop: acc += A @ B^T over K (single fp16 stream) ----------------
#define GEMM_MAINLOOP(KDIM, SRC_A, SRC_B)                                          \
    const int C = (KDIM) / 64;                                                     \
    const int rowL  = tid >> 1;                                                    \
    const int cBase = (tid & 1) * 4;                                               \
    const char* srcA = SRC_A;                                                      \
    const char* srcB = SRC_B;                                                      \
    uint32_t dsto[4];                                                              \
    _Pragma("unroll")                                                              \
    for (int t = 0; t < 4; t++)                                                    \
        dsto[t] = SW128((uint32_t)(rowL * 128 + (cBase + t) * 16));                \
    _Pragma("unroll")                                                              \
    for (int c = 0; c < 2; c++) {                                                  \
        uint32_t sb = ub + c * STAGE_BYTES;                                        \
        size_t ko = (size_t)c * 128;                                               \
        _Pragma("unroll")                                                          \
        for (int t = 0; t < 4; t++) {                                              \
            CP16(sb + dsto[t],              srcA + ko + t * 16);                   \
            CP16(sb + TILE_BYTES + dsto[t], srcB + ko + t * 16);                   \
        }                                                                          \
        CP_COMMIT();                                                               \
    }                                                                              \
    const int wm = (wid & 3) * 32;                                                 \
    const int wn = (wid >> 2) * 64;                                                \
    uint32_t aoffs[2], boffs[4];                                                   \
    _Pragma("unroll")                                                              \
    for (int mi = 0; mi < 2; mi++)                                                 \
        aoffs[mi] = SW128((uint32_t)((wm + mi * 16 + (lane & 15)) * 128            \
                                     + (lane >> 4) * 16));                         \
    _Pragma("unroll")                                                              \
    for (int nq = 0; nq < 4; nq++)                                                 \
        boffs[nq] = SW128((uint32_t)((wn + nq * 16 + (lane & 15)) * 128            \
                                     + (lane >> 4) * 16)) + TILE_BYTES;            \
    float acc[2][8][4];                                                            \
    _Pragma("unroll")                                                              \
    for (int i = 0; i < 2; i++)                                                    \
        _Pragma("unroll")                                                          \
        for (int j = 0; j < 8; j++)                                                \
            _Pragma("unroll")                                                      \
            for (int q = 0; q < 4; q++) acc[i][j][q] = 0.f;                        \
    for (int c = 0; c < C; c++) {                                                  \
        if (c >= C - 2) { CP_WAIT0(); } else { CP_WAIT1(); }                       \
        __syncthreads();                                                           \
        int cn = c + 2;                                                            \
        if (cn < C) {                                                              \
            uint32_t sb = ub + (cn % NSTAGE) * STAGE_BYTES;                        \
            size_t ko = (size_t)cn * 128;                                          \
            _Pragma("unroll")                                                      \
            for (int t = 0; t < 4; t++) {                                          \
                CP16(sb + dsto[t],              srcA + ko + t * 16);               \
                CP16(sb + TILE_BYTES + dsto[t], srcB + ko + t * 16);               \
            }                                                                      \
            CP_COMMIT();                                                           \
        }                                                                          \
        uint32_t sbase = ub + (c % NSTAGE) * STAGE_BYTES;                          \
        _Pragma("unroll")                                                          \
        for (int kk = 0; kk < 4; kk++) {                                           \
            uint32_t a[2][4], b[4][4];                                             \
            _Pragma("unroll")                                                      \
            for (int mi = 0; mi < 2; mi++)                                         \
                LDSM4(a[mi][0], a[mi][1], a[mi][2], a[mi][3],                      \
                      sbase + (aoffs[mi] ^ (kk * 32)));                            \
            _Pragma("unroll")                                                      \
            for (int nq = 0; nq < 4; nq++)                                         \
                LDSM4(b[nq][0], b[nq][1], b[nq][2], b[nq][3],                      \
                      sbase + (boffs[nq] ^ (kk * 32)));                            \
            _Pragma("unroll")                                                      \
            for (int mi = 0; mi < 2; mi++)                                         \
                _Pragma("unroll")                                                  \
                for (int nq = 0; nq < 4; nq++) {                                   \
                    MMA16816(acc[mi][nq * 2],     a[mi][0], a[mi][1], a[mi][2],    \
                             a[mi][3], b[nq][0], b[nq][2]);                        \
                    MMA16816(acc[mi][nq * 2 + 1], a[mi][0], a[mi][1], a[mi][2],    \
                             a[mi][3], b[nq][1], b[nq][3]);                        \
                }                                                                  \
        }                                                                          \
    }

// GEMM1: h[aid] = silu(x[tok] @ w1[e]^T + b1[e]) -> fp16
__global__ __launch_bounds__(256, 2) void gemm1_mma(const float* __restrict__ b1) {
    const int e   = blockIdx.z;
    const int cnt = g_cnt[e];
    const int m0  = blockIdx.x * BM;
    if (m0 >= cnt) return;
    const int n0  = blockIdx.y * BN;

    extern __shared__ char dsm[];
    char* base = (char*)(((uintptr_t)dsm + 1023) & ~(uintptr_t)1023);
    int* sAsg = (int*)base;
    uint32_t ub = smem_u32(base) + 3072;

    const int tid = threadIdx.x, wid = tid >> 5, lane = tid & 31;
    if (tid < BM) {
        int r = m0 + tid;
        sAsg[tid] = (r < cnt) ? g_asg[e][r] : -1;
    }
    __syncthreads();

    int aidL = sAsg[tid >> 1];
    int tokL = (aidL >= 0) ? (aidL >> 1) : 0;
    size_t aoff = ((size_t)tokL * D_DIM + (size_t)(tid & 1) * 32) * 2;
    size_t boff = (((size_t)e * H_DIM + n0 + (tid >> 1)) * D_DIM + (size_t)(tid & 1) * 32) * 2;

    GEMM_MAINLOOP(D_DIM,
        (const char*)g_xh + aoff,
        (const char*)g_w1h + boff)

    const float* b1e = b1 + (size_t)e * H_DIM + n0;
    float bias[8][2];
#pragma unroll
    for (int ni = 0; ni < 8; ni++) {
        int cb = wn + ni * 8 + (lane & 3) * 2;
        bias[ni][0] = __ldg(b1e + cb);
        bias[ni][1] = __ldg(b1e + cb + 1);
    }
#pragma unroll
    for (int mi = 0; mi < 2; mi++) {
#pragma unroll
        for (int h = 0; h < 2; h++) {
            int row = wm + mi * 16 + (lane >> 2) + h * 8;
            int aid = sAsg[row];
            if (aid < 0) continue;
            __half* hh = g_hh + (size_t)aid * H_DIM + n0;
#pragma unroll
            for (int ni = 0; ni < 8; ni++) {
                int cb = wn + ni * 8 + (lane & 3) * 2;
                float v0 = acc[mi][ni][h * 2]     + bias[ni][0];
                float v1 = acc[mi][ni][h * 2 + 1] + bias[ni][1];
                v0 = v0 / (1.f + __expf(-v0));
                v1 = v1 / (1.f + __expf(-v1));
                __half2 p = __floats2half2_rn(v0, v1);
                *(uint32_t*)(hh + cb) = *(uint32_t*)&p;
            }
        }
    }
}

// GEMM2: out[tok] += gate * ( h[aid] @ w2[e]^T + b2[e] )
__global__ __launch_bounds__(256, 2) void gemm2_mma(const float* __restrict__ b2,
                                                    float* __restrict__ out) {
    const int e   = blockIdx.z;
    const int cnt = g_cnt[e];
    const int m0  = blockIdx.x * BM;
    if (m0 >= cnt) return;
    const int n0  = blockIdx.y * BN;

    extern __shared__ char dsm[];
    char* base = (char*)(((uintptr_t)dsm + 1023) & ~(uintptr_t)1023);
    int*   sAsg  = (int*)base;
    float* sGate = (float*)(base + 512);
    uint32_t ub = smem_u32(base) + 3072;

    const int tid = threadIdx.x, wid = tid >> 5, lane = tid & 31;
    if (tid < BM) {
        int r = m0 + tid;
        sAsg[tid]  = (r < cnt) ? g_asg[e][r] : -1;
        sGate[tid] = (r < cnt) ? g_gate[e][r] : 0.f;
    }
    __syncthreads();

    int aidL = sAsg[tid >> 1];
    int arwL = (aidL >= 0) ? aidL : 0;
    size_t aoff = ((size_t)arwL * H_DIM + (size_t)(tid & 1) * 32) * 2;
    size_t boff = (((size_t)e * D_DIM + n0 + (tid >> 1)) * H_DIM + (size_t)(tid & 1) * 32) * 2;

    GEMM_MAINLOOP(H_DIM,
        (const char*)g_hh + aoff,
        (const char*)g_w2h + boff)

    const float* b2e = b2 + (size_t)e * D_DIM + n0;
    float bias[8][2];
#pragma unroll
    for (int ni = 0; ni < 8; ni++) {
        int cb = wn + ni * 8 + (lane & 3) * 2;
        bias[ni][0] = __ldg(b2e + cb);
        bias[ni][1] = __ldg(b2e + cb + 1);
    }
#pragma unroll
    for (int mi = 0; mi < 2; mi++) {
#pragma unroll
        for (int h = 0; h < 2; h++) {
            int row = wm + mi * 16 + (lane >> 2) + h * 8;
            int aid = sAsg[row];
            if (aid < 0) continue;
            float gte = sGate[row];
            float* orow = out + (size_t)(aid >> 1) * D_DIM + n0;
#pragma unroll
            for (int ni = 0; ni < 8; ni++) {
                int cb = wn + ni * 8 + (lane & 3) * 2;
                atomicAdd(orow + cb,     gte * (acc[mi][ni][h * 2]     + bias[ni][0]));
                atomicAdd(orow + cb + 1, gte * (acc[mi][ni][h * 2 + 1] + bias[ni][1]));
            }
        }
    }
}

// ---------------- launch ----------------
extern "C" void kernel_launch(void* const* d_in, const int* in_sizes, int n_in,
                              void* d_out, int out_size) {
    const float* x  = (const float*)d_in[0];
    const float* gw = (const float*)d_in[1];
    const float* w1 = (const float*)d_in[2];
    const float* b1 = (const float*)d_in[3];
    const float* w2 = (const float*)d_in[4];
    const float* b2 = (const float*)d_in[5];
    float* out = (float*)d_out;

    cudaFuncSetAttribute(gemm1_mma, cudaFuncAttributeMaxDynamicSharedMemorySize, SMEM_DYN);
    cudaFuncSetAttribute(gemm2_mma, cudaFuncAttributeMaxDynamicSharedMemorySize, SMEM_DYN);

    cudaMemsetAsync(out, 0, (size_t)N_TOK * D_DIM * sizeof(float), 0);

    init_kernel<<<1, 32>>>();
    gating_kernel<<<N_TOK / 8, 256>>>(x, gw);

    int total4 = NX4 + NW14 + NW24;
    split_all_kernel<<<(total4 + 255) / 256, 256>>>((const float4*)x, (const float4*)w1,
                                                    (const float4*)w2);

    dim3 g1(N_TOK / BM, H_DIM / BN, E_NUM);   // (32, 16, 8)
    gemm1_mma<<<g1, 256, SMEM_DYN>>>(b1);

    // gemm2 in the ncu capture window this round
    dim3 g2(N_TOK / BM, D_DIM / BN, E_NUM);   // (32, 8, 8)
    gemm2_mma<<<g2, 256, SMEM_DYN>>>(b2, out);

    aux_kernel<<<1, 1>>>(out + (out_size - 1));
}